// round 3
// baseline (speedup 1.0000x reference)
#include <cuda_runtime.h>

#define BB 4
#define CC 128
#define HW 4096
#define NG 8

// Scratch (allocation-free rule: __device__ globals)
__device__ float g_qkv[(size_t)BB * 3 * CC * HW];   // [b][3C][HW]  ~25 MB
__device__ float g_att[(size_t)BB * CC * HW];       // [b][C][HW]   ~8 MB
__device__ float g_mean[BB * NG];
__device__ float g_rstd[BB * NG];

// ---------------------------------------------------------------------------
// Kernel 1: per-(batch,group) mean / rstd.  Group = contiguous 16*4096 floats.
// ---------------------------------------------------------------------------
__global__ __launch_bounds__(256) void k_stats(const float* __restrict__ x) {
    int bg = blockIdx.x;                      // 0..31
    const float4* base = (const float4*)(x + (size_t)bg * 16 * HW);
    float s = 0.f, ss = 0.f;
    for (int i = threadIdx.x; i < 16 * HW / 4; i += 256) {
        float4 v = base[i];
        s  += (v.x + v.y) + (v.z + v.w);
        ss += (v.x * v.x + v.y * v.y) + (v.z * v.z + v.w * v.w);
    }
    __shared__ float rs[256], rss[256];
    rs[threadIdx.x] = s; rss[threadIdx.x] = ss;
    __syncthreads();
    for (int o = 128; o > 0; o >>= 1) {
        if (threadIdx.x < o) {
            rs[threadIdx.x]  += rs[threadIdx.x + o];
            rss[threadIdx.x] += rss[threadIdx.x + o];
        }
        __syncthreads();
    }
    if (threadIdx.x == 0) {
        float m   = rs[0]  * (1.f / 65536.f);
        float var = rss[0] * (1.f / 65536.f) - m * m;
        g_mean[bg] = m;
        g_rstd[bg] = rsqrtf(var + 1e-5f);
    }
}

// ---------------------------------------------------------------------------
// Kernel 2: qkv = qkv_w @ groupnorm(x) + qkv_b
// Per batch: [384 x 4096] = [384 x 128] @ [128 x 4096]. Tile 64(out) x 64(spatial).
// ---------------------------------------------------------------------------
#define GEMM_SMEM ((128 * 65 + 128 * 64) * 4)

__global__ __launch_bounds__(256) void k_qkv(const float* __restrict__ x,
                                             const float* __restrict__ nw,
                                             const float* __restrict__ nb,
                                             const float* __restrict__ w,
                                             const float* __restrict__ bias) {
    extern __shared__ float sm[];
    float* Ws = sm;                 // [128][65]  W transposed: Ws[c][r]
    float* Xs = sm + 128 * 65;      // [128][64]  normalized x: Xs[c][s]
    int s0 = blockIdx.x << 6;
    int o0 = blockIdx.y << 6;
    int b  = blockIdx.z;
    int t  = threadIdx.x;

    // Load W tile transposed (pitch 65 -> conflict-free transposed writes)
    for (int e = t; e < 2048; e += 256) {
        int r = e >> 5, c4 = (e & 31) << 2;
        float4 v = *(const float4*)(w + (o0 + r) * CC + c4);
        Ws[(c4 + 0) * 65 + r] = v.x;
        Ws[(c4 + 1) * 65 + r] = v.y;
        Ws[(c4 + 2) * 65 + r] = v.z;
        Ws[(c4 + 3) * 65 + r] = v.w;
    }
    // Load x tile, apply GroupNorm on the fly
    for (int e = t; e < 2048; e += 256) {
        int c = e >> 4, s4 = (e & 15) << 2;
        float4 v = *(const float4*)(x + ((size_t)b * CC + c) * HW + s0 + s4);
        int bg = b * NG + (c >> 4);
        float ga = nw[c] * g_rstd[bg];
        float be = nb[c] - g_mean[bg] * ga;
        v.x = fmaf(v.x, ga, be); v.y = fmaf(v.y, ga, be);
        v.z = fmaf(v.z, ga, be); v.w = fmaf(v.w, ga, be);
        *(float4*)&Xs[c * 64 + s4] = v;
    }
    __syncthreads();

    int tx = t & 15, ty = t >> 4;
    float acc[4][4] = {};
#pragma unroll 4
    for (int c = 0; c < CC; c++) {
        float4 xv = *(const float4*)&Xs[c * 64 + (tx << 2)];
#pragma unroll
        for (int i = 0; i < 4; i++) {
            float wv = Ws[c * 65 + (ty << 2) + i];
            acc[i][0] = fmaf(wv, xv.x, acc[i][0]);
            acc[i][1] = fmaf(wv, xv.y, acc[i][1]);
            acc[i][2] = fmaf(wv, xv.z, acc[i][2]);
            acc[i][3] = fmaf(wv, xv.w, acc[i][3]);
        }
    }
#pragma unroll
    for (int i = 0; i < 4; i++) {
        int o = o0 + (ty << 2) + i;
        float bb = bias[o];
        float4 v = make_float4(acc[i][0] + bb, acc[i][1] + bb,
                               acc[i][2] + bb, acc[i][3] + bb);
        *(float4*)(g_qkv + ((size_t)b * 3 * CC + o) * HW + s0 + (tx << 2)) = v;
    }
}

// ---------------------------------------------------------------------------
// Kernel 3: flash attention. 64 queries/CTA, 64-key tiles, d=128.
// Q,K channel-major in smem; V token-major (transposed, pitch 132).
// ---------------------------------------------------------------------------
#define ATTN_SMEM (29440 * 4)
#define SCALE 0.08838834764831845f

__global__ __launch_bounds__(256, 1) void k_attn() {
    extern __shared__ float sm[];
    float* Qs   = sm;           // [128][64]
    float* Ks   = sm + 8192;    // [128][64]
    float* Vs   = sm + 16384;   // [64][132]
    float* Ps   = sm + 24832;   // [64][65]
    float* red  = sm + 28992;   // [4][64]
    float* rmax = sm + 29248;   // [64]
    float* rsum = sm + 29312;   // [64]
    float* corr = sm + 29376;   // [64]

    int n0 = blockIdx.x << 6;
    int b  = blockIdx.y;
    int t  = threadIdx.x;
    int tx = t & 15, ty = t >> 4;
    const float* qbase = g_qkv + (size_t)b * 3 * CC * HW;
    const float* kbase = qbase + (size_t)CC * HW;
    const float* vbase = qbase + (size_t)2 * CC * HW;

    // Load Q tile: Qs[c][n]
    for (int e = t; e < 2048; e += 256) {
        int c = e >> 4, n4 = (e & 15) << 2;
        *(float4*)&Qs[c * 64 + n4] = *(const float4*)(qbase + (size_t)c * HW + n0 + n4);
    }
    if (t < 64) { rmax[t] = -1e30f; rsum[t] = 0.f; }

    float acc[4][8] = {};       // O[n=4*ty+i][c=8*tx+j]

    for (int m0 = 0; m0 < HW; m0 += 64) {
        __syncthreads();  // (A) previous tile fully consumed; Q ready (iter 0)
        // Load K tile: Ks[c][m]
        for (int e = t; e < 2048; e += 256) {
            int c = e >> 4, m4 = (e & 15) << 2;
            *(float4*)&Ks[c * 64 + m4] = *(const float4*)(kbase + (size_t)c * HW + m0 + m4);
        }
        // Load V tile transposed: Vs[m][c], pitch 132
        for (int e = t; e < 2048; e += 256) {
            int c = e >> 4, m4 = (e & 15) << 2;
            float4 v = *(const float4*)(vbase + (size_t)c * HW + m0 + m4);
            Vs[(m4 + 0) * 132 + c] = v.x;
            Vs[(m4 + 1) * 132 + c] = v.y;
            Vs[(m4 + 2) * 132 + c] = v.z;
            Vs[(m4 + 3) * 132 + c] = v.w;
        }
        __syncthreads();  // (B)

        // S = scale * Q^T K : thread -> rows 4*ty+i, cols 4*tx+j
        float s_acc[4][4] = {};
#pragma unroll 8
        for (int c = 0; c < 128; c++) {
            float4 qv = *(const float4*)&Qs[c * 64 + (ty << 2)];
            float4 kv = *(const float4*)&Ks[c * 64 + (tx << 2)];
            s_acc[0][0] = fmaf(qv.x, kv.x, s_acc[0][0]);
            s_acc[0][1] = fmaf(qv.x, kv.y, s_acc[0][1]);
            s_acc[0][2] = fmaf(qv.x, kv.z, s_acc[0][2]);
            s_acc[0][3] = fmaf(qv.x, kv.w, s_acc[0][3]);
            s_acc[1][0] = fmaf(qv.y, kv.x, s_acc[1][0]);
            s_acc[1][1] = fmaf(qv.y, kv.y, s_acc[1][1]);
            s_acc[1][2] = fmaf(qv.y, kv.z, s_acc[1][2]);
            s_acc[1][3] = fmaf(qv.y, kv.w, s_acc[1][3]);
            s_acc[2][0] = fmaf(qv.z, kv.x, s_acc[2][0]);
            s_acc[2][1] = fmaf(qv.z, kv.y, s_acc[2][1]);
            s_acc[2][2] = fmaf(qv.z, kv.z, s_acc[2][2]);
            s_acc[2][3] = fmaf(qv.z, kv.w, s_acc[2][3]);
            s_acc[3][0] = fmaf(qv.w, kv.x, s_acc[3][0]);
            s_acc[3][1] = fmaf(qv.w, kv.y, s_acc[3][1]);
            s_acc[3][2] = fmaf(qv.w, kv.z, s_acc[3][2]);
            s_acc[3][3] = fmaf(qv.w, kv.w, s_acc[3][3]);
        }
#pragma unroll
        for (int i = 0; i < 4; i++)
#pragma unroll
            for (int j = 0; j < 4; j++)
                Ps[((ty << 2) + i) * 65 + (tx << 2) + j] = s_acc[i][j] * SCALE;
        __syncthreads();  // (C) Ps ready

        // Online softmax. row = t&63, quarter q = t>>6 covers 16 cols.
        int row = t & 63, qd = t >> 6;
        float pm = -1e30f;
#pragma unroll
        for (int j = 0; j < 16; j++) pm = fmaxf(pm, Ps[row * 65 + (qd << 4) + j]);
        red[(qd << 6) + row] = pm;
        __syncthreads();  // (D)
        if (t < 64) {
            float mo = rmax[t];
            float mt = fmaxf(fmaxf(red[t], red[64 + t]), fmaxf(red[128 + t], red[192 + t]));
            float mn = fmaxf(mo, mt);
            rmax[t] = mn;
            corr[t] = __expf(mo - mn);
        }
        __syncthreads();  // (E) rmax/corr ready
        float mn = rmax[row];
        float psum = 0.f;
#pragma unroll
        for (int j = 0; j < 16; j++) {
            float p = __expf(Ps[row * 65 + (qd << 4) + j] - mn);
            Ps[row * 65 + (qd << 4) + j] = p;
            psum += p;
        }
        red[(qd << 6) + row] = psum;
        __syncthreads();  // (F) exp(P) + partial sums ready
        if (t < 64)
            rsum[t] = rsum[t] * corr[t] + red[t] + red[64 + t] + red[128 + t] + red[192 + t];

        // Rescale O accumulators, then accumulate P @ V
        float cr[4];
#pragma unroll
        for (int i = 0; i < 4; i++) cr[i] = corr[(ty << 2) + i];
#pragma unroll
        for (int i = 0; i < 4; i++)
#pragma unroll
            for (int j = 0; j < 8; j++) acc[i][j] *= cr[i];

#pragma unroll 4
        for (int m = 0; m < 64; m++) {
            float pv0 = Ps[((ty << 2) + 0) * 65 + m];
            float pv1 = Ps[((ty << 2) + 1) * 65 + m];
            float pv2 = Ps[((ty << 2) + 2) * 65 + m];
            float pv3 = Ps[((ty << 2) + 3) * 65 + m];
            float4 v0 = *(const float4*)&Vs[m * 132 + (tx << 3)];
            float4 v1 = *(const float4*)&Vs[m * 132 + (tx << 3) + 4];
            acc[0][0] = fmaf(pv0, v0.x, acc[0][0]); acc[0][1] = fmaf(pv0, v0.y, acc[0][1]);
            acc[0][2] = fmaf(pv0, v0.z, acc[0][2]); acc[0][3] = fmaf(pv0, v0.w, acc[0][3]);
            acc[0][4] = fmaf(pv0, v1.x, acc[0][4]); acc[0][5] = fmaf(pv0, v1.y, acc[0][5]);
            acc[0][6] = fmaf(pv0, v1.z, acc[0][6]); acc[0][7] = fmaf(pv0, v1.w, acc[0][7]);
            acc[1][0] = fmaf(pv1, v0.x, acc[1][0]); acc[1][1] = fmaf(pv1, v0.y, acc[1][1]);
            acc[1][2] = fmaf(pv1, v0.z, acc[1][2]); acc[1][3] = fmaf(pv1, v0.w, acc[1][3]);
            acc[1][4] = fmaf(pv1, v1.x, acc[1][4]); acc[1][5] = fmaf(pv1, v1.y, acc[1][5]);
            acc[1][6] = fmaf(pv1, v1.z, acc[1][6]); acc[1][7] = fmaf(pv1, v1.w, acc[1][7]);
            acc[2][0] = fmaf(pv2, v0.x, acc[2][0]); acc[2][1] = fmaf(pv2, v0.y, acc[2][1]);
            acc[2][2] = fmaf(pv2, v0.z, acc[2][2]); acc[2][3] = fmaf(pv2, v0.w, acc[2][3]);
            acc[2][4] = fmaf(pv2, v1.x, acc[2][4]); acc[2][5] = fmaf(pv2, v1.y, acc[2][5]);
            acc[2][6] = fmaf(pv2, v1.z, acc[2][6]); acc[2][7] = fmaf(pv2, v1.w, acc[2][7]);
            acc[3][0] = fmaf(pv3, v0.x, acc[3][0]); acc[3][1] = fmaf(pv3, v0.y, acc[3][1]);
            acc[3][2] = fmaf(pv3, v0.z, acc[3][2]); acc[3][3] = fmaf(pv3, v0.w, acc[3][3]);
            acc[3][4] = fmaf(pv3, v1.x, acc[3][4]); acc[3][5] = fmaf(pv3, v1.y, acc[3][5]);
            acc[3][6] = fmaf(pv3, v1.z, acc[3][6]); acc[3][7] = fmaf(pv3, v1.w, acc[3][7]);
        }
    }
    __syncthreads();  // final rsum visible

#pragma unroll
    for (int i = 0; i < 4; i++) {
        int n = (ty << 2) + i;
        float inv = 1.f / rsum[n];
#pragma unroll
        for (int j = 0; j < 8; j++) {
            int c = (tx << 3) + j;
            g_att[((size_t)b * CC + c) * HW + n0 + n] = acc[i][j] * inv;
        }
    }
}

// ---------------------------------------------------------------------------
// Kernel 4: out = x + proj_w @ att + proj_b
// ---------------------------------------------------------------------------
__global__ __launch_bounds__(256) void k_proj(const float* __restrict__ x,
                                              const float* __restrict__ w,
                                              const float* __restrict__ bias,
                                              float* __restrict__ out) {
    extern __shared__ float sm[];
    float* Ws = sm;                 // [128][65]
    float* Xs = sm + 128 * 65;      // [128][64]
    int s0 = blockIdx.x << 6;
    int o0 = blockIdx.y << 6;
    int b  = blockIdx.z;
    int t  = threadIdx.x;

    for (int e = t; e < 2048; e += 256) {
        int r = e >> 5, c4 = (e & 31) << 2;
        float4 v = *(const float4*)(w + (o0 + r) * CC + c4);
        Ws[(c4 + 0) * 65 + r] = v.x;
        Ws[(c4 + 1) * 65 + r] = v.y;
        Ws[(c4 + 2) * 65 + r] = v.z;
        Ws[(c4 + 3) * 65 + r] = v.w;
    }
    for (int e = t; e < 2048; e += 256) {
        int c = e >> 4, s4 = (e & 15) << 2;
        *(float4*)&Xs[c * 64 + s4] =
            *(const float4*)(g_att + ((size_t)b * CC + c) * HW + s0 + s4);
    }
    __syncthreads();

    int tx = t & 15, ty = t >> 4;
    float acc[4][4] = {};
#pragma unroll 4
    for (int c = 0; c < CC; c++) {
        float4 xv = *(const float4*)&Xs[c * 64 + (tx << 2)];
#pragma unroll
        for (int i = 0; i < 4; i++) {
            float wv = Ws[c * 65 + (ty << 2) + i];
            acc[i][0] = fmaf(wv, xv.x, acc[i][0]);
            acc[i][1] = fmaf(wv, xv.y, acc[i][1]);
            acc[i][2] = fmaf(wv, xv.z, acc[i][2]);
            acc[i][3] = fmaf(wv, xv.w, acc[i][3]);
        }
    }
#pragma unroll
    for (int i = 0; i < 4; i++) {
        int o = o0 + (ty << 2) + i;
        float bb = bias[o];
        size_t off = ((size_t)b * CC + o) * HW + s0 + (tx << 2);
        float4 r = *(const float4*)(x + off);
        float4 v = make_float4(acc[i][0] + bb + r.x, acc[i][1] + bb + r.y,
                               acc[i][2] + bb + r.z, acc[i][3] + bb + r.w);
        *(float4*)(out + off) = v;
    }
}

// ---------------------------------------------------------------------------
extern "C" void kernel_launch(void* const* d_in, const int* in_sizes, int n_in,
                              void* d_out, int out_size) {
    const float* x  = (const float*)d_in[0];
    const float* nw = (const float*)d_in[1];
    const float* nb = (const float*)d_in[2];
    const float* qw = (const float*)d_in[3];
    const float* qb = (const float*)d_in[4];
    const float* pw = (const float*)d_in[5];
    const float* pb = (const float*)d_in[6];
    float* out = (float*)d_out;

    // Host-side, capture-safe, idempotent.
    cudaFuncSetAttribute(k_qkv,  cudaFuncAttributeMaxDynamicSharedMemorySize, GEMM_SMEM);
    cudaFuncSetAttribute(k_proj, cudaFuncAttributeMaxDynamicSharedMemorySize, GEMM_SMEM);
    cudaFuncSetAttribute(k_attn, cudaFuncAttributeMaxDynamicSharedMemorySize, ATTN_SMEM);

    k_stats<<<32, 256>>>(x);
    k_qkv<<<dim3(64, 6, BB), 256, GEMM_SMEM>>>(x, nw, nb, qw, qb);
    k_attn<<<dim3(64, BB), 256, ATTN_SMEM>>>();
    k_proj<<<dim3(64, 2, BB), 256, GEMM_SMEM>>>(x, pw, pb, out);
}

// round 16
// speedup vs baseline: 6.5210x; 6.5210x over previous
#include <cuda_runtime.h>
#include <cuda_bf16.h>
#include <cstdint>

#define BB 4
#define CC 128
#define HW 4096
#define NG 8
#define SCALE 0.08838834764831845f

// Scratch (allocation-free rule: __device__ globals)
__device__ __nv_bfloat16 g_q[(size_t)BB * HW * CC];   // [b][tok][c] bf16, pre-scaled
__device__ __nv_bfloat16 g_k[(size_t)BB * HW * CC];   // [b][tok][c] bf16
__device__ __nv_bfloat16 g_v[(size_t)BB * CC * HW];   // [b][c][tok] bf16
__device__ float g_att[(size_t)BB * HW * CC];         // [b][tok][c] fp32 (token-major)
__device__ float g_mean[BB * NG];
__device__ float g_rstd[BB * NG];

// One dynamic-shared symbol for the whole TU (extern shared arrays alias).
extern __shared__ char dynsm[];

// ---------------------------------------------------------------------------
// Helpers (base-PTX only: no tcgen05 — harness builds compute_103 PTX)
// ---------------------------------------------------------------------------
__device__ __forceinline__ uint32_t smem_u32(const void* p) {
    uint32_t a;
    asm("{ .reg .u64 t; cvta.to.shared.u64 t, %1; cvt.u32.u64 %0, t; }" : "=r"(a) : "l"(p));
    return a;
}
__device__ __forceinline__ void ldm4(uint32_t& r0, uint32_t& r1, uint32_t& r2,
                                     uint32_t& r3, uint32_t a) {
    asm volatile("ldmatrix.sync.aligned.m8n8.x4.shared.b16 {%0,%1,%2,%3}, [%4];"
                 : "=r"(r0), "=r"(r1), "=r"(r2), "=r"(r3) : "r"(a));
}
__device__ __forceinline__ void mma_bf16(float c[4], const uint32_t a[4],
                                         uint32_t b0, uint32_t b1) {
    asm volatile(
        "mma.sync.aligned.m16n8k16.row.col.f32.bf16.bf16.f32 "
        "{%0,%1,%2,%3}, {%4,%5,%6,%7}, {%8,%9}, {%0,%1,%2,%3};"
        : "+f"(c[0]), "+f"(c[1]), "+f"(c[2]), "+f"(c[3])
        : "r"(a[0]), "r"(a[1]), "r"(a[2]), "r"(a[3]), "r"(b0), "r"(b1));
}
__device__ __forceinline__ uint32_t pkbf2(float lo, float hi) {
    __nv_bfloat162 h = __floats2bfloat162_rn(lo, hi);
    return *(uint32_t*)&h;
}

// ---------------------------------------------------------------------------
// Kernel 1: per-(batch,group) mean / rstd
// ---------------------------------------------------------------------------
__global__ __launch_bounds__(256) void k_stats(const float* __restrict__ x) {
    int bg = blockIdx.x;
    const float4* base = (const float4*)(x + (size_t)bg * 16 * HW);
    float s = 0.f, ss = 0.f;
    for (int i = threadIdx.x; i < 16 * HW / 4; i += 256) {
        float4 v = base[i];
        s  += (v.x + v.y) + (v.z + v.w);
        ss += (v.x * v.x + v.y * v.y) + (v.z * v.z + v.w * v.w);
    }
    __shared__ float rs[256], rss[256];
    rs[threadIdx.x] = s; rss[threadIdx.x] = ss;
    __syncthreads();
    for (int o = 128; o > 0; o >>= 1) {
        if (threadIdx.x < o) {
            rs[threadIdx.x]  += rs[threadIdx.x + o];
            rss[threadIdx.x] += rss[threadIdx.x + o];
        }
        __syncthreads();
    }
    if (threadIdx.x == 0) {
        float m   = rs[0]  * (1.f / 65536.f);
        float var = rss[0] * (1.f / 65536.f) - m * m;
        g_mean[bg] = m;
        g_rstd[bg] = rsqrtf(var + 1e-5f);
    }
}

// ---------------------------------------------------------------------------
// Kernel 2: qkv = qkv_w @ groupnorm(x) + qkv_b  -> bf16 q/k/v
// ---------------------------------------------------------------------------
#define GEMM_SMEM ((128 * 65 + 128 * 64) * 4)

__global__ __launch_bounds__(256) void k_qkv(const float* __restrict__ x,
                                             const float* __restrict__ nw,
                                             const float* __restrict__ nb,
                                             const float* __restrict__ w,
                                             const float* __restrict__ bias) {
    float* smf = (float*)dynsm;
    float* Ws = smf;                 // [128][65]
    float* Xs = smf + 128 * 65;      // [128][64]
    int s0 = blockIdx.x << 6;
    int o0 = blockIdx.y << 6;
    int b  = blockIdx.z;
    int t  = threadIdx.x;

    for (int e = t; e < 2048; e += 256) {
        int r = e >> 5, c4 = (e & 31) << 2;
        float4 v = *(const float4*)(w + (o0 + r) * CC + c4);
        Ws[(c4 + 0) * 65 + r] = v.x;
        Ws[(c4 + 1) * 65 + r] = v.y;
        Ws[(c4 + 2) * 65 + r] = v.z;
        Ws[(c4 + 3) * 65 + r] = v.w;
    }
    for (int e = t; e < 2048; e += 256) {
        int c = e >> 4, s4 = (e & 15) << 2;
        float4 v = *(const float4*)(x + ((size_t)b * CC + c) * HW + s0 + s4);
        int bg = b * NG + (c >> 4);
        float ga = nw[c] * g_rstd[bg];
        float be = nb[c] - g_mean[bg] * ga;
        v.x = fmaf(v.x, ga, be); v.y = fmaf(v.y, ga, be);
        v.z = fmaf(v.z, ga, be); v.w = fmaf(v.w, ga, be);
        *(float4*)&Xs[c * 64 + s4] = v;
    }
    __syncthreads();

    int tx = t & 15, ty = t >> 4;
    float acc[4][4] = {};
#pragma unroll 4
    for (int c = 0; c < CC; c++) {
        float4 xv = *(const float4*)&Xs[c * 64 + (tx << 2)];
#pragma unroll
        for (int i = 0; i < 4; i++) {
            float wv = Ws[c * 65 + (ty << 2) + i];
            acc[i][0] = fmaf(wv, xv.x, acc[i][0]);
            acc[i][1] = fmaf(wv, xv.y, acc[i][1]);
            acc[i][2] = fmaf(wv, xv.z, acc[i][2]);
            acc[i][3] = fmaf(wv, xv.w, acc[i][3]);
        }
    }
    int ob = o0 + (ty << 2);
    float b0 = bias[ob], b1 = bias[ob + 1], b2 = bias[ob + 2], b3 = bias[ob + 3];
    if (o0 < 128) {                 // Q: token-major, softmax scale folded
#pragma unroll
        for (int j = 0; j < 4; j++) {
            int s = s0 + (tx << 2) + j;
            uint2 u;
            u.x = pkbf2((acc[0][j] + b0) * SCALE, (acc[1][j] + b1) * SCALE);
            u.y = pkbf2((acc[2][j] + b2) * SCALE, (acc[3][j] + b3) * SCALE);
            *(uint2*)(&g_q[((size_t)b * HW + s) * CC + ob]) = u;
        }
    } else if (o0 < 256) {          // K: token-major
#pragma unroll
        for (int j = 0; j < 4; j++) {
            int s = s0 + (tx << 2) + j;
            uint2 u;
            u.x = pkbf2(acc[0][j] + b0, acc[1][j] + b1);
            u.y = pkbf2(acc[2][j] + b2, acc[3][j] + b3);
            *(uint2*)(&g_k[((size_t)b * HW + s) * CC + (ob - 128)]) = u;
        }
    } else {                        // V: channel-major
#pragma unroll
        for (int i = 0; i < 4; i++) {
            float bb = bias[ob + i];
            uint2 u;
            u.x = pkbf2(acc[i][0] + bb, acc[i][1] + bb);
            u.y = pkbf2(acc[i][2] + bb, acc[i][3] + bb);
            *(uint2*)(&g_v[((size_t)b * CC + ob + i - 256) * HW + s0 + (tx << 2)]) = u;
        }
    }
}

// ---------------------------------------------------------------------------
// Kernel 3: FA2-style bf16 flash attention on mma.sync (HMMA).
// 128 queries/CTA (8 warps x 16 rows), 64-key tiles, d=128.
// ---------------------------------------------------------------------------
#define OFF_Q 0                 // 128 q x 256B (plain)
#define OFF_K 32768             // 64 tok x 256B (chunk^row swizzle)
#define OFF_V 49152             // 128 c x 128B (chunk^row swizzle)
#define ATTN_SMEM 65536

__global__ __launch_bounds__(256, 1) void k_attn() {
    char* sm = dynsm;
    uint32_t sb = smem_u32(sm);
    int t = threadIdx.x, w = t >> 5, l = t & 31;
    int b = blockIdx.y, n0 = blockIdx.x << 7;

    const __nv_bfloat16* qb = g_q + ((size_t)b * HW + n0) * CC;
    const __nv_bfloat16* kb = g_k + (size_t)b * HW * CC;
    const __nv_bfloat16* vb = g_v + (size_t)b * CC * HW;

    // Q tile -> smem (plain; one-time, conflicts OK)
#pragma unroll
    for (int j = 0; j < 8; j++) {
        int e = t + (j << 8);
        *(uint4*)(sm + OFF_Q + (e >> 4) * 256 + ((e & 15) << 4)) =
            *(const uint4*)(qb + (size_t)(e >> 4) * CC + ((e & 15) << 3));
    }
    __syncthreads();

    // Persistent Q A-fragments: qa[kstep][4]
    uint32_t qa[8][4];
    {
        uint32_t base = sb + OFF_Q + (16 * w + (l & 15)) * 256 + ((l >> 4) << 4);
#pragma unroll
        for (int kk = 0; kk < 8; kk++)
            ldm4(qa[kk][0], qa[kk][1], qa[kk][2], qa[kk][3], base + kk * 32);
    }

    float oa[16][4];
#pragma unroll
    for (int j = 0; j < 16; j++)
        oa[j][0] = oa[j][1] = oa[j][2] = oa[j][3] = 0.f;
    float m0r = -1e30f, m1r = -1e30f, l0r = 0.f, l1r = 0.f;

    // ldmatrix lane geometry (shared by K and V B-fragment loads)
    int roff = (l & 7) + ((l & 16) >> 1);   // row within 16-row group
    int half = (l >> 3) & 1;                // low/high k-chunk
    int sxor = l & 7;                       // swizzle xor (== row & 7)
    uint32_t kfb = sb + OFF_K + roff * 256;
    uint32_t vfb = sb + OFF_V + roff * 128;

    // Prefetch tile 0 into registers
    uint4 kr[4], vr[4];
#pragma unroll
    for (int j = 0; j < 4; j++) {
        int e = t + (j << 8);
        kr[j] = *(const uint4*)(kb + (size_t)(e >> 4) * CC + ((e & 15) << 3));
        vr[j] = *(const uint4*)(vb + (size_t)(e >> 3) * HW + ((e & 7) << 3));
    }

    for (int m0 = 0; m0 < HW; m0 += 64) {
        __syncthreads();                    // prev tile fully consumed
#pragma unroll
        for (int j = 0; j < 4; j++) {       // regs -> swizzled smem
            int e = t + (j << 8);
            int kt = e >> 4, kc = e & 15;
            *(uint4*)(sm + OFF_K + kt * 256 + ((kc ^ (kt & 7)) << 4)) = kr[j];
            int vc = e >> 3, vk = e & 7;
            *(uint4*)(sm + OFF_V + vc * 128 + ((vk ^ (vc & 7)) << 4)) = vr[j];
        }
        __syncthreads();                    // tile ready
        if (m0 + 64 < HW) {                 // prefetch next (overlaps MMA)
#pragma unroll
            for (int j = 0; j < 4; j++) {
                int e = t + (j << 8);
                kr[j] = *(const uint4*)(kb + (size_t)(m0 + 64 + (e >> 4)) * CC + ((e & 15) << 3));
                vr[j] = *(const uint4*)(vb + (size_t)(e >> 3) * HW + m0 + 64 + ((e & 7) << 3));
            }
        }

        // ---- S = Q @ K^T : warp rows [16w,16w+16), all 64 keys ----
        float sa[8][4];
#pragma unroll
        for (int j = 0; j < 8; j++)
            sa[j][0] = sa[j][1] = sa[j][2] = sa[j][3] = 0.f;
#pragma unroll
        for (int ng = 0; ng < 4; ng++) {
#pragma unroll
            for (int kk = 0; kk < 8; kk++) {
                uint32_t b0, b1, b2, b3;
                ldm4(b0, b1, b2, b3,
                     kfb + (ng << 12) + ((((kk << 1) + half) ^ sxor) << 4));
                mma_bf16(sa[2 * ng],     qa[kk], b0, b1);
                mma_bf16(sa[2 * ng + 1], qa[kk], b2, b3);
            }
        }

        // ---- online softmax (registers + quad shuffles only) ----
        float mx0 = fmaxf(sa[0][0], sa[0][1]);
        float mx1 = fmaxf(sa[0][2], sa[0][3]);
#pragma unroll
        for (int j = 1; j < 8; j++) {
            mx0 = fmaxf(mx0, fmaxf(sa[j][0], sa[j][1]));
            mx1 = fmaxf(mx1, fmaxf(sa[j][2], sa[j][3]));
        }
        mx0 = fmaxf(mx0, __shfl_xor_sync(0xffffffffu, mx0, 1));
        mx0 = fmaxf(mx0, __shfl_xor_sync(0xffffffffu, mx0, 2));
        mx1 = fmaxf(mx1, __shfl_xor_sync(0xffffffffu, mx1, 1));
        mx1 = fmaxf(mx1, __shfl_xor_sync(0xffffffffu, mx1, 2));
        float mn0 = fmaxf(m0r, mx0), mn1 = fmaxf(m1r, mx1);
        float c0 = __expf(m0r - mn0), c1 = __expf(m1r - mn1);
        m0r = mn0; m1r = mn1;
        float ps0 = 0.f, ps1 = 0.f;
#pragma unroll
        for (int j = 0; j < 8; j++) {
            sa[j][0] = __expf(sa[j][0] - mn0);
            sa[j][1] = __expf(sa[j][1] - mn0);
            sa[j][2] = __expf(sa[j][2] - mn1);
            sa[j][3] = __expf(sa[j][3] - mn1);
            ps0 += sa[j][0] + sa[j][1];
            ps1 += sa[j][2] + sa[j][3];
        }
        ps0 += __shfl_xor_sync(0xffffffffu, ps0, 1);
        ps0 += __shfl_xor_sync(0xffffffffu, ps0, 2);
        ps1 += __shfl_xor_sync(0xffffffffu, ps1, 1);
        ps1 += __shfl_xor_sync(0xffffffffu, ps1, 2);
        l0r = l0r * c0 + ps0;
        l1r = l1r * c1 + ps1;

        // P fp32 C-frag -> bf16 A-frag (FA2 identity), rescale O
        uint32_t pa[4][4];
#pragma unroll
        for (int ks = 0; ks < 4; ks++) {
            pa[ks][0] = pkbf2(sa[2 * ks][0],     sa[2 * ks][1]);
            pa[ks][1] = pkbf2(sa[2 * ks][2],     sa[2 * ks][3]);
            pa[ks][2] = pkbf2(sa[2 * ks + 1][0], sa[2 * ks + 1][1]);
            pa[ks][3] = pkbf2(sa[2 * ks + 1][2], sa[2 * ks + 1][3]);
        }
#pragma unroll
        for (int j = 0; j < 16; j++) {
            oa[j][0] *= c0; oa[j][1] *= c0;
            oa[j][2] *= c1; oa[j][3] *= c1;
        }

        // ---- O += P @ V^T ----
#pragma unroll
        for (int cg = 0; cg < 8; cg++) {
#pragma unroll
            for (int ks = 0; ks < 4; ks++) {
                uint32_t b0, b1, b2, b3;
                ldm4(b0, b1, b2, b3,
                     vfb + (cg << 11) + ((((ks << 1) + half) ^ sxor) << 4));
                mma_bf16(oa[2 * cg],     pa[ks], b0, b1);
                mma_bf16(oa[2 * cg + 1], pa[ks], b2, b3);
            }
        }
    }

    // Epilogue: token-major fp32 output, 8B-contiguous stores
    float inv0 = 1.f / l0r, inv1 = 1.f / l1r;
    float* op = g_att + ((size_t)b * HW + n0 + 16 * w + (l >> 2)) * CC + ((l & 3) << 1);
#pragma unroll
    for (int j = 0; j < 16; j++) {
        *(float2*)(op + (j << 3)) = make_float2(oa[j][0] * inv0, oa[j][1] * inv0);
        *(float2*)(op + 8 * CC + (j << 3)) = make_float2(oa[j][2] * inv1, oa[j][3] * inv1);
    }
}

// ---------------------------------------------------------------------------
// Kernel 4: out = x + proj_w @ att + proj_b   (att is token-major)
// ---------------------------------------------------------------------------
__global__ __launch_bounds__(256) void k_proj(const float* __restrict__ x,
                                              const float* __restrict__ w,
                                              const float* __restrict__ bias,
                                              float* __restrict__ out) {
    float* smf = (float*)dynsm;
    float* Ws = smf;
    float* Xs = smf + 128 * 65;
    int s0 = blockIdx.x << 6;
    int o0 = blockIdx.y << 6;
    int b  = blockIdx.z;
    int t  = threadIdx.x;

    for (int e = t; e < 2048; e += 256) {
        int r = e >> 5, c4 = (e & 31) << 2;
        float4 v = *(const float4*)(w + (o0 + r) * CC + c4);
        Ws[(c4 + 0) * 65 + r] = v.x;
        Ws[(c4 + 1) * 65 + r] = v.y;
        Ws[(c4 + 2) * 65 + r] = v.z;
        Ws[(c4 + 3) * 65 + r] = v.w;
    }
    // transpose-on-load: g_att[tok][c] -> Xs[c][s]
    for (int e = t; e < 2048; e += 256) {
        int s = e >> 5, c4 = (e & 31) << 2;
        float4 v = *(const float4*)(g_att + ((size_t)b * HW + s0 + s) * CC + c4);
        Xs[(c4 + 0) * 64 + s] = v.x;
        Xs[(c4 + 1) * 64 + s] = v.y;
        Xs[(c4 + 2) * 64 + s] = v.z;
        Xs[(c4 + 3) * 64 + s] = v.w;
    }
    __syncthreads();

    int tx = t & 15, ty = t >> 4;
    float acc[4][4] = {};
#pragma unroll 4
    for (int c = 0; c < CC; c++) {
        float4 xv = *(const float4*)&Xs[c * 64 + (tx << 2)];
#pragma unroll
        for (int i = 0; i < 4; i++) {
            float wv = Ws[c * 65 + (ty << 2) + i];
            acc[i][0] = fmaf(wv, xv.x, acc[i][0]);
            acc[i][1] = fmaf(wv, xv.y, acc[i][1]);
            acc[i][2] = fmaf(wv, xv.z, acc[i][2]);
            acc[i][3] = fmaf(wv, xv.w, acc[i][3]);
        }
    }
#pragma unroll
    for (int i = 0; i < 4; i++) {
        int o = o0 + (ty << 2) + i;
        float bb = bias[o];
        size_t off = ((size_t)b * CC + o) * HW + s0 + (tx << 2);
        float4 r = *(const float4*)(x + off);
        float4 v = make_float4(acc[i][0] + bb + r.x, acc[i][1] + bb + r.y,
                               acc[i][2] + bb + r.z, acc[i][3] + bb + r.w);
        *(float4*)(out + off) = v;
    }
}

// ---------------------------------------------------------------------------
extern "C" void kernel_launch(void* const* d_in, const int* in_sizes, int n_in,
                              void* d_out, int out_size) {
    const float* x  = (const float*)d_in[0];
    const float* nw = (const float*)d_in[1];
    const float* nb = (const float*)d_in[2];
    const float* qw = (const float*)d_in[3];
    const float* qb = (const float*)d_in[4];
    const float* pw = (const float*)d_in[5];
    const float* pb = (const float*)d_in[6];
    float* out = (float*)d_out;

    cudaFuncSetAttribute(k_qkv,  cudaFuncAttributeMaxDynamicSharedMemorySize, GEMM_SMEM);
    cudaFuncSetAttribute(k_proj, cudaFuncAttributeMaxDynamicSharedMemorySize, GEMM_SMEM);
    cudaFuncSetAttribute(k_attn, cudaFuncAttributeMaxDynamicSharedMemorySize, ATTN_SMEM);

    k_stats<<<32, 256>>>(x);
    k_qkv<<<dim3(64, 6, BB), 256, GEMM_SMEM>>>(x, nw, nb, qw, qb);
    k_attn<<<dim3(32, BB), 256, ATTN_SMEM>>>();
    k_proj<<<dim3(64, 2, BB), 256, GEMM_SMEM>>>(x, pw, pb, out);
}

// round 17
// speedup vs baseline: 10.3635x; 1.5892x over previous
#include <cuda_runtime.h>
#include <cuda_bf16.h>
#include <cstdint>

#define BB 4
#define CC 128
#define HW 4096
#define NG 8
#define SCALE 0.08838834764831845f

// Scratch (allocation-free rule: __device__ globals)
__device__ __nv_bfloat16 g_q[(size_t)BB * HW * CC];   // [b][tok][c] bf16, pre-scaled
__device__ __nv_bfloat16 g_k[(size_t)BB * HW * CC];   // [b][tok][c] bf16
__device__ __nv_bfloat16 g_v[(size_t)BB * CC * HW];   // [b][c][tok] bf16
__device__ float g_mean[BB * NG];
__device__ float g_rstd[BB * NG];

// One dynamic-shared symbol for the whole TU (extern shared arrays alias).
extern __shared__ char dynsm[];

// ---------------------------------------------------------------------------
// Helpers (base-PTX only: no tcgen05 — harness builds compute_103 PTX)
// ---------------------------------------------------------------------------
__device__ __forceinline__ uint32_t smem_u32(const void* p) {
    uint32_t a;
    asm("{ .reg .u64 t; cvta.to.shared.u64 t, %1; cvt.u32.u64 %0, t; }" : "=r"(a) : "l"(p));
    return a;
}
__device__ __forceinline__ void ldm4(uint32_t& r0, uint32_t& r1, uint32_t& r2,
                                     uint32_t& r3, uint32_t a) {
    asm volatile("ldmatrix.sync.aligned.m8n8.x4.shared.b16 {%0,%1,%2,%3}, [%4];"
                 : "=r"(r0), "=r"(r1), "=r"(r2), "=r"(r3) : "r"(a));
}
__device__ __forceinline__ void mma_bf16(float c[4], const uint32_t a[4],
                                         uint32_t b0, uint32_t b1) {
    asm volatile(
        "mma.sync.aligned.m16n8k16.row.col.f32.bf16.bf16.f32 "
        "{%0,%1,%2,%3}, {%4,%5,%6,%7}, {%8,%9}, {%0,%1,%2,%3};"
        : "+f"(c[0]), "+f"(c[1]), "+f"(c[2]), "+f"(c[3])
        : "r"(a[0]), "r"(a[1]), "r"(a[2]), "r"(a[3]), "r"(b0), "r"(b1));
}
__device__ __forceinline__ uint32_t pkbf2(float lo, float hi) {
    __nv_bfloat162 h = __floats2bfloat162_rn(lo, hi);
    return *(uint32_t*)&h;
}

// Load a 128x128 fp32 weight block (row-major [o][c]) into bf16 swizzled smem
// ([o][c], 256B rows, 16B chunk ^= o&7). Also stage 128 fp32 biases.
__device__ __forceinline__ void load_wchunk(const float* __restrict__ wsrc,
                                            char* WS, float* bs,
                                            const float* __restrict__ bsrc, int t) {
#pragma unroll
    for (int i = 0; i < 8; i++) {
        int e = t + (i << 8);
        int o = e >> 4, ck = e & 15;
        const float* p = wsrc + (size_t)o * CC + (ck << 3);
        float4 w0 = *(const float4*)p;
        float4 w1 = *(const float4*)(p + 4);
        uint4 u;
        u.x = pkbf2(w0.x, w0.y); u.y = pkbf2(w0.z, w0.w);
        u.z = pkbf2(w1.x, w1.y); u.w = pkbf2(w1.z, w1.w);
        *(uint4*)(WS + o * 256 + ((ck ^ (o & 7)) << 4)) = u;
    }
    if (t < 128) bs[t] = bsrc[t];
}

// ---------------------------------------------------------------------------
// Kernel 1: per-(batch,group) mean / rstd
// ---------------------------------------------------------------------------
__global__ __launch_bounds__(256) void k_stats(const float* __restrict__ x) {
    int bg = blockIdx.x;
    const float4* base = (const float4*)(x + (size_t)bg * 16 * HW);
    float s = 0.f, ss = 0.f;
    for (int i = threadIdx.x; i < 16 * HW / 4; i += 256) {
        float4 v = base[i];
        s  += (v.x + v.y) + (v.z + v.w);
        ss += (v.x * v.x + v.y * v.y) + (v.z * v.z + v.w * v.w);
    }
    __shared__ float rs[256], rss[256];
    rs[threadIdx.x] = s; rss[threadIdx.x] = ss;
    __syncthreads();
    for (int o = 128; o > 0; o >>= 1) {
        if (threadIdx.x < o) {
            rs[threadIdx.x]  += rs[threadIdx.x + o];
            rss[threadIdx.x] += rss[threadIdx.x + o];
        }
        __syncthreads();
    }
    if (threadIdx.x == 0) {
        float m   = rs[0]  * (1.f / 65536.f);
        float var = rss[0] * (1.f / 65536.f) - m * m;
        g_mean[bg] = m;
        g_rstd[bg] = rsqrtf(var + 1e-5f);
    }
}

// ---------------------------------------------------------------------------
// Kernel 2: qkv = qkv_w @ groupnorm(x) + qkv_b  (HMMA bf16)
// Grid (32 token-tiles, 4 batch), 256 thr. Per CTA: xn [128tok][128c] bf16,
// then 3 weight chunks. q,k: A=xn,B=W -> C[tok][o]. v: A=W,B=xn -> C[o][tok].
// ---------------------------------------------------------------------------
#define QKV_XN 0
#define QKV_WS 32768
#define QKV_BS 65536
#define QKV_SMEM 66048

__global__ __launch_bounds__(256, 1) void k_qkv(const float* __restrict__ x,
                                                const float* __restrict__ nw,
                                                const float* __restrict__ nb,
                                                const float* __restrict__ wq,
                                                const float* __restrict__ bias) {
    char* sm = dynsm;
    char* XN = sm + QKV_XN;
    char* WS = sm + QKV_WS;
    float* bs = (float*)(sm + QKV_BS);
    uint32_t sb = smem_u32(sm);
    int t = threadIdx.x, wi = t >> 5, l = t & 31;
    int b = blockIdx.y, n0 = blockIdx.x << 7;

    // GroupNorm + transpose to token-major bf16 swizzled smem
#pragma unroll
    for (int i = 0; i < 8; i++) {
        int e = t + (i << 8);
        int cp = e & 63, tq = e >> 6;
        int c0 = cp << 1, tok = tq << 2;
        float4 va = *(const float4*)(x + ((size_t)b * CC + c0) * HW + n0 + tok);
        float4 vb = *(const float4*)(x + ((size_t)b * CC + c0 + 1) * HW + n0 + tok);
        int bg = b * NG + (c0 >> 4);
        float rst = g_rstd[bg], mn = g_mean[bg];
        float ga0 = nw[c0] * rst,     be0 = nb[c0]     - mn * ga0;
        float ga1 = nw[c0 + 1] * rst, be1 = nb[c0 + 1] - mn * ga1;
        float a0 = fmaf(va.x, ga0, be0), a1 = fmaf(va.y, ga0, be0);
        float a2 = fmaf(va.z, ga0, be0), a3 = fmaf(va.w, ga0, be0);
        float b0 = fmaf(vb.x, ga1, be1), b1 = fmaf(vb.y, ga1, be1);
        float b2 = fmaf(vb.z, ga1, be1), b3 = fmaf(vb.w, ga1, be1);
        uint32_t u[4] = {pkbf2(a0, b0), pkbf2(a1, b1), pkbf2(a2, b2), pkbf2(a3, b3)};
        int ck = cp >> 2, wd = (cp & 3) << 2;
#pragma unroll
        for (int q = 0; q < 4; q++) {
            int row = tok + q;
            *(uint32_t*)(XN + row * 256 + ((ck ^ (row & 7)) << 4) + wd) = u[q];
        }
    }

    int roff = (l & 7) + ((l & 16) >> 1);
    int half = (l >> 3) & 1;
    int sx = l & 7;
    uint32_t xnb = sb + QKV_XN, wsb = sb + QKV_WS;

    // ---- chunk 0/1: q and k ----
    uint32_t aa[8][4];   // A-frags of xn, rows 16wi..16wi+15 (loaded after sync)
#pragma unroll
    for (int sec = 0; sec < 2; sec++) {
        load_wchunk(wq + (size_t)sec * 128 * CC, WS, bs, bias + sec * 128, t);
        __syncthreads();                      // xn (sec 0) + W chunk ready
        if (sec == 0) {
            int row = 16 * wi + (l & 15);
            uint32_t ab = xnb + row * 256;
#pragma unroll
            for (int kk = 0; kk < 8; kk++)
                ldm4(aa[kk][0], aa[kk][1], aa[kk][2], aa[kk][3],
                     ab + ((((kk << 1) + (l >> 4)) ^ (row & 7)) << 4));
        }
        float ca[16][4];
#pragma unroll
        for (int j = 0; j < 16; j++)
            ca[j][0] = ca[j][1] = ca[j][2] = ca[j][3] = 0.f;
        uint32_t wfb = wsb + roff * 256;
#pragma unroll
        for (int ng = 0; ng < 8; ng++) {
#pragma unroll
            for (int kk = 0; kk < 8; kk++) {
                uint32_t b0, b1, b2, b3;
                ldm4(b0, b1, b2, b3, wfb + (ng << 12) + ((((kk << 1) + half) ^ sx) << 4));
                mma_bf16(ca[2 * ng],     aa[kk], b0, b1);
                mma_bf16(ca[2 * ng + 1], aa[kk], b2, b3);
            }
        }
        float sc = sec == 0 ? SCALE : 1.f;
        __nv_bfloat16* dst = (sec == 0 ? g_q : g_k) +
            ((size_t)b * HW + n0 + 16 * wi + (l >> 2)) * CC;
#pragma unroll
        for (int ng = 0; ng < 8; ng++) {
            int o = 16 * ng + ((l & 3) << 1);
            float p0 = bs[o], p1 = bs[o + 1], p8 = bs[o + 8], p9 = bs[o + 9];
            *(uint32_t*)(dst + o) = pkbf2((ca[2*ng][0] + p0) * sc, (ca[2*ng][1] + p1) * sc);
            *(uint32_t*)(dst + 8 * CC + o) = pkbf2((ca[2*ng][2] + p0) * sc, (ca[2*ng][3] + p1) * sc);
            *(uint32_t*)(dst + o + 8) = pkbf2((ca[2*ng+1][0] + p8) * sc, (ca[2*ng+1][1] + p9) * sc);
            *(uint32_t*)(dst + 8 * CC + o + 8) = pkbf2((ca[2*ng+1][2] + p8) * sc, (ca[2*ng+1][3] + p9) * sc);
        }
        __syncthreads();                      // done reading WS before reload
    }

    // ---- chunk 2: v (A=W rows=o, B=xn cols=tok) ----
    load_wchunk(wq + (size_t)2 * 128 * CC, WS, bs, bias + 256, t);
    __syncthreads();
    {
        int row = 16 * wi + (l & 15);
        uint32_t ab = wsb + row * 256;
        uint32_t aw[8][4];
#pragma unroll
        for (int kk = 0; kk < 8; kk++)
            ldm4(aw[kk][0], aw[kk][1], aw[kk][2], aw[kk][3],
                 ab + ((((kk << 1) + (l >> 4)) ^ (row & 7)) << 4));
        float ca[16][4];
#pragma unroll
        for (int j = 0; j < 16; j++)
            ca[j][0] = ca[j][1] = ca[j][2] = ca[j][3] = 0.f;
        uint32_t xfb = xnb + roff * 256;
#pragma unroll
        for (int ng = 0; ng < 8; ng++) {
#pragma unroll
            for (int kk = 0; kk < 8; kk++) {
                uint32_t b0, b1, b2, b3;
                ldm4(b0, b1, b2, b3, xfb + (ng << 12) + ((((kk << 1) + half) ^ sx) << 4));
                mma_bf16(ca[2 * ng],     aw[kk], b0, b1);
                mma_bf16(ca[2 * ng + 1], aw[kk], b2, b3);
            }
        }
        int ov = 16 * wi + (l >> 2);
        float bv0 = bs[ov], bv1 = bs[ov + 8];
        __nv_bfloat16* dst = g_v + ((size_t)b * CC + ov) * HW + n0;
#pragma unroll
        for (int ng = 0; ng < 8; ng++) {
            int tc = 16 * ng + ((l & 3) << 1);
            *(uint32_t*)(dst + tc) = pkbf2(ca[2*ng][0] + bv0, ca[2*ng][1] + bv0);
            *(uint32_t*)(dst + 8 * HW + tc) = pkbf2(ca[2*ng][2] + bv1, ca[2*ng][3] + bv1);
            *(uint32_t*)(dst + tc + 8) = pkbf2(ca[2*ng+1][0] + bv0, ca[2*ng+1][1] + bv0);
            *(uint32_t*)(dst + 8 * HW + tc + 8) = pkbf2(ca[2*ng+1][2] + bv1, ca[2*ng+1][3] + bv1);
        }
    }
}

// ---------------------------------------------------------------------------
// Kernel 3: FA2 bf16 flash attention + fused proj + residual (HMMA).
// 128 queries/CTA (8 warps x 16 rows), 64-key tiles, d=128.
// ---------------------------------------------------------------------------
#define OFF_Q  0                 // 128 q x 256B (plain)
#define OFF_K  32768             // 64 tok x 256B (chunk^row swizzle)
#define OFF_V  49152             // 128 c x 128B (chunk^row swizzle)
#define OFF_WP 65536             // proj_w [o][c] bf16 swizzled
#define OFF_PB 98304             // proj bias fp32
#define ATTN_SMEM 98816

__global__ __launch_bounds__(256, 1) void k_attn(const float* __restrict__ xres,
                                                 const float* __restrict__ pw,
                                                 const float* __restrict__ pb,
                                                 float* __restrict__ out) {
    char* sm = dynsm;
    uint32_t sb = smem_u32(sm);
    int t = threadIdx.x, w = t >> 5, l = t & 31;
    int b = blockIdx.y, n0 = blockIdx.x << 7;

    const __nv_bfloat16* qb = g_q + ((size_t)b * HW + n0) * CC;
    const __nv_bfloat16* kb = g_k + (size_t)b * HW * CC;
    const __nv_bfloat16* vb = g_v + (size_t)b * CC * HW;

    // Q tile -> smem (plain; one-time) and proj weights -> swizzled smem
#pragma unroll
    for (int j = 0; j < 8; j++) {
        int e = t + (j << 8);
        *(uint4*)(sm + OFF_Q + (e >> 4) * 256 + ((e & 15) << 4)) =
            *(const uint4*)(qb + (size_t)(e >> 4) * CC + ((e & 15) << 3));
    }
    load_wchunk(pw, sm + OFF_WP, (float*)(sm + OFF_PB), pb, t);
    __syncthreads();

    // Persistent Q A-fragments
    uint32_t qa[8][4];
    {
        uint32_t base = sb + OFF_Q + (16 * w + (l & 15)) * 256 + ((l >> 4) << 4);
#pragma unroll
        for (int kk = 0; kk < 8; kk++)
            ldm4(qa[kk][0], qa[kk][1], qa[kk][2], qa[kk][3], base + kk * 32);
    }

    float oa[16][4];
#pragma unroll
    for (int j = 0; j < 16; j++)
        oa[j][0] = oa[j][1] = oa[j][2] = oa[j][3] = 0.f;
    float m0r = -1e30f, m1r = -1e30f, l0r = 0.f, l1r = 0.f;

    int roff = (l & 7) + ((l & 16) >> 1);
    int half = (l >> 3) & 1;
    int sx = l & 7;
    uint32_t kfb = sb + OFF_K + roff * 256;
    uint32_t vfb = sb + OFF_V + roff * 128;

    // Prefetch tile 0 into registers
    uint4 kr[4], vr[4];
#pragma unroll
    for (int j = 0; j < 4; j++) {
        int e = t + (j << 8);
        kr[j] = *(const uint4*)(kb + (size_t)(e >> 4) * CC + ((e & 15) << 3));
        vr[j] = *(const uint4*)(vb + (size_t)(e >> 3) * HW + ((e & 7) << 3));
    }

    for (int m0 = 0; m0 < HW; m0 += 64) {
        __syncthreads();
#pragma unroll
        for (int j = 0; j < 4; j++) {
            int e = t + (j << 8);
            int kt = e >> 4, kc = e & 15;
            *(uint4*)(sm + OFF_K + kt * 256 + ((kc ^ (kt & 7)) << 4)) = kr[j];
            int vc = e >> 3, vk = e & 7;
            *(uint4*)(sm + OFF_V + vc * 128 + ((vk ^ (vc & 7)) << 4)) = vr[j];
        }
        __syncthreads();
        if (m0 + 64 < HW) {
#pragma unroll
            for (int j = 0; j < 4; j++) {
                int e = t + (j << 8);
                kr[j] = *(const uint4*)(kb + (size_t)(m0 + 64 + (e >> 4)) * CC + ((e & 15) << 3));
                vr[j] = *(const uint4*)(vb + (size_t)(e >> 3) * HW + m0 + 64 + ((e & 7) << 3));
            }
        }

        // ---- S = Q @ K^T ----
        float sa[8][4];
#pragma unroll
        for (int j = 0; j < 8; j++)
            sa[j][0] = sa[j][1] = sa[j][2] = sa[j][3] = 0.f;
#pragma unroll
        for (int ng = 0; ng < 4; ng++) {
#pragma unroll
            for (int kk = 0; kk < 8; kk++) {
                uint32_t b0, b1, b2, b3;
                ldm4(b0, b1, b2, b3,
                     kfb + (ng << 12) + ((((kk << 1) + half) ^ sx) << 4));
                mma_bf16(sa[2 * ng],     qa[kk], b0, b1);
                mma_bf16(sa[2 * ng + 1], qa[kk], b2, b3);
            }
        }

        // ---- online softmax (registers + quad shuffles) ----
        float mx0 = fmaxf(sa[0][0], sa[0][1]);
        float mx1 = fmaxf(sa[0][2], sa[0][3]);
#pragma unroll
        for (int j = 1; j < 8; j++) {
            mx0 = fmaxf(mx0, fmaxf(sa[j][0], sa[j][1]));
            mx1 = fmaxf(mx1, fmaxf(sa[j][2], sa[j][3]));
        }
        mx0 = fmaxf(mx0, __shfl_xor_sync(0xffffffffu, mx0, 1));
        mx0 = fmaxf(mx0, __shfl_xor_sync(0xffffffffu, mx0, 2));
        mx1 = fmaxf(mx1, __shfl_xor_sync(0xffffffffu, mx1, 1));
        mx1 = fmaxf(mx1, __shfl_xor_sync(0xffffffffu, mx1, 2));
        float mn0 = fmaxf(m0r, mx0), mn1 = fmaxf(m1r, mx1);
        float c0 = __expf(m0r - mn0), c1 = __expf(m1r - mn1);
        m0r = mn0; m1r = mn1;
        float ps0 = 0.f, ps1 = 0.f;
#pragma unroll
        for (int j = 0; j < 8; j++) {
            sa[j][0] = __expf(sa[j][0] - mn0);
            sa[j][1] = __expf(sa[j][1] - mn0);
            sa[j][2] = __expf(sa[j][2] - mn1);
            sa[j][3] = __expf(sa[j][3] - mn1);
            ps0 += sa[j][0] + sa[j][1];
            ps1 += sa[j][2] + sa[j][3];
        }
        ps0 += __shfl_xor_sync(0xffffffffu, ps0, 1);
        ps0 += __shfl_xor_sync(0xffffffffu, ps0, 2);
        ps1 += __shfl_xor_sync(0xffffffffu, ps1, 1);
        ps1 += __shfl_xor_sync(0xffffffffu, ps1, 2);
        l0r = l0r * c0 + ps0;
        l1r = l1r * c1 + ps1;

        // P fp32 C-frag -> bf16 A-frag, rescale O
        uint32_t pa[4][4];
#pragma unroll
        for (int ks = 0; ks < 4; ks++) {
            pa[ks][0] = pkbf2(sa[2 * ks][0],     sa[2 * ks][1]);
            pa[ks][1] = pkbf2(sa[2 * ks][2],     sa[2 * ks][3]);
            pa[ks][2] = pkbf2(sa[2 * ks + 1][0], sa[2 * ks + 1][1]);
            pa[ks][3] = pkbf2(sa[2 * ks + 1][2], sa[2 * ks + 1][3]);
        }
#pragma unroll
        for (int j = 0; j < 16; j++) {
            oa[j][0] *= c0; oa[j][1] *= c0;
            oa[j][2] *= c1; oa[j][3] *= c1;
        }

        // ---- O += P @ V^T ----
#pragma unroll
        for (int cg = 0; cg < 8; cg++) {
#pragma unroll
            for (int ks = 0; ks < 4; ks++) {
                uint32_t b0, b1, b2, b3;
                ldm4(b0, b1, b2, b3,
                     vfb + (cg << 11) + ((((ks << 1) + half) ^ sx) << 4));
                mma_bf16(oa[2 * cg],     pa[ks], b0, b1);
                mma_bf16(oa[2 * cg + 1], pa[ks], b2, b3);
            }
        }
    }

    // ---- fused proj: normalize O -> bf16 A-frags, GEMM vs proj_w ----
    float inv0 = 1.f / l0r, inv1 = 1.f / l1r;
    uint32_t po[8][4];
#pragma unroll
    for (int kk = 0; kk < 8; kk++) {
        po[kk][0] = pkbf2(oa[2*kk][0]   * inv0, oa[2*kk][1]   * inv0);
        po[kk][1] = pkbf2(oa[2*kk][2]   * inv1, oa[2*kk][3]   * inv1);
        po[kk][2] = pkbf2(oa[2*kk+1][0] * inv0, oa[2*kk+1][1] * inv0);
        po[kk][3] = pkbf2(oa[2*kk+1][2] * inv1, oa[2*kk+1][3] * inv1);
    }
    float c2[16][4];
#pragma unroll
    for (int j = 0; j < 16; j++)
        c2[j][0] = c2[j][1] = c2[j][2] = c2[j][3] = 0.f;
    uint32_t wpb = sb + OFF_WP + roff * 256;
#pragma unroll
    for (int ng = 0; ng < 8; ng++) {
#pragma unroll
        for (int kk = 0; kk < 8; kk++) {
            uint32_t b0, b1, b2, b3;
            ldm4(b0, b1, b2, b3, wpb + (ng << 12) + ((((kk << 1) + half) ^ sx) << 4));
            mma_bf16(c2[2 * ng],     po[kk], b0, b1);
            mma_bf16(c2[2 * ng + 1], po[kk], b2, b3);
        }
    }

    // bias + residual + store (out is channel-major [b][o][tok])
    const float* pbs = (const float*)(sm + OFF_PB);
    int tok = n0 + 16 * w + (l >> 2);
#pragma unroll
    for (int ng = 0; ng < 8; ng++) {
        int o = 16 * ng + ((l & 3) << 1);
        float p0 = pbs[o], p1 = pbs[o + 1], p8 = pbs[o + 8], p9 = pbs[o + 9];
        size_t i0 = ((size_t)b * CC + o) * HW + tok;
        size_t i8 = i0 + (size_t)8 * HW;
        out[i0]          = c2[2*ng][0]   + p0 + xres[i0];
        out[i0 + HW]     = c2[2*ng][1]   + p1 + xres[i0 + HW];
        out[i0 + 8]      = c2[2*ng][2]   + p0 + xres[i0 + 8];
        out[i0 + HW + 8] = c2[2*ng][3]   + p1 + xres[i0 + HW + 8];
        out[i8]          = c2[2*ng+1][0] + p8 + xres[i8];
        out[i8 + HW]     = c2[2*ng+1][1] + p9 + xres[i8 + HW];
        out[i8 + 8]      = c2[2*ng+1][2] + p8 + xres[i8 + 8];
        out[i8 + HW + 8] = c2[2*ng+1][3] + p9 + xres[i8 + HW + 8];
    }
}

// ---------------------------------------------------------------------------
extern "C" void kernel_launch(void* const* d_in, const int* in_sizes, int n_in,
                              void* d_out, int out_size) {
    const float* x  = (const float*)d_in[0];
    const float* nw = (const float*)d_in[1];
    const float* nb = (const float*)d_in[2];
    const float* qw = (const float*)d_in[3];
    const float* qb = (const float*)d_in[4];
    const float* pw = (const float*)d_in[5];
    const float* pb = (const float*)d_in[6];
    float* out = (float*)d_out;

    cudaFuncSetAttribute(k_qkv,  cudaFuncAttributeMaxDynamicSharedMemorySize, QKV_SMEM);
    cudaFuncSetAttribute(k_attn, cudaFuncAttributeMaxDynamicSharedMemorySize, ATTN_SMEM);

    k_stats<<<32, 256>>>(x);
    k_qkv<<<dim3(32, BB), 256, QKV_SMEM>>>(x, nw, nb, qw, qb);
    k_attn<<<dim3(32, BB), 256, ATTN_SMEM>>>(x, pw, pb, out);
}